// round 6
// baseline (speedup 1.0000x reference)
#include <cuda_runtime.h>
#include <cstdint>

// Idx2PixelLayer: bilinear gather of N=1e6 points from a 2048x2048x8 fp32 image.
// c = ((coord - 1) mod (dim - 4)) + 1   (non-negative mod, JAX semantics)
// out = w00*g(0,0) + w10*g(1,0) + w01*g(0,1) + w11*g(1,1)
//   w00=d0*d1, w10=(1-d0)*d1, w01=d0*(1-d1), w11=(1-d0)*(1-d1)
// Reference's off-mask is always false (c <= 2045 < 2048), so dropped.
//
// Layout: 2 threads per point-slot; thread half k (=t&1) handles channels 4k..4k+3,
// so lane pairs cover one 32B pixel sector per gather (1 L1tex wavefront/point/gather).
// Each thread processes TWO points (p and p + n/2) with all 8 gathers front-batched
// for deep MLP -> higher DRAM queue occupancy (R4 showed we're BW-latency limited,
// not L2-capacity fixable: evict_last pinning was neutral).

static constexpr int H = 2048;
static constexpr int W = 2048;
static constexpr int C = 8;

struct PointCtx {
    int   base;   // float offset of g(0,0) + channel half
    float w00, w10, w01, w11;
};

__device__ __forceinline__ PointCtx make_ctx(float2 xy, int k) {
    const float m0 = (float)(H - 4);   // 2044
    const float m1 = (float)(W - 4);

    float c0 = fmodf(xy.x - 1.0f, m0); if (c0 < 0.0f) c0 += m0; c0 += 1.0f;
    float c1 = fmodf(xy.y - 1.0f, m1); if (c1 < 0.0f) c1 += m1; c1 += 1.0f;

    float f0 = floorf(c0);
    float f1 = floorf(c1);
    float d0 = c0 - f0;
    float d1 = c1 - f1;
    int   i0 = (int)f0;
    int   i1 = (int)f1;

    PointCtx ctx;
    ctx.base = (i0 * W + i1) * C + 4 * k;
    ctx.w00 = d0 * d1;
    ctx.w10 = (1.0f - d0) * d1;
    ctx.w01 = d0 * (1.0f - d1);
    ctx.w11 = (1.0f - d0) * (1.0f - d1);
    return ctx;
}

__device__ __forceinline__ float4 blend(const PointCtx& c,
                                        float4 a00, float4 a01,
                                        float4 a10, float4 a11) {
    float4 o;
    o.x = c.w00 * a00.x + c.w10 * a10.x + c.w01 * a01.x + c.w11 * a11.x;
    o.y = c.w00 * a00.y + c.w10 * a10.y + c.w01 * a01.y + c.w11 * a11.y;
    o.z = c.w00 * a00.z + c.w10 * a10.z + c.w01 * a01.z + c.w11 * a11.z;
    o.w = c.w00 * a00.w + c.w10 * a10.w + c.w01 * a01.w + c.w11 * a11.w;
    return o;
}

__global__ __launch_bounds__(256)
void idx2pixel_kernel(const float* __restrict__ coords,
                      const float* __restrict__ visible,
                      float* __restrict__ out,
                      int n)  // n = number of points
{
    int t = blockIdx.x * blockDim.x + threadIdx.x;
    int half = (n + 1) >> 1;          // points per pass
    int pA = t >> 1;                  // first point
    int k  = t & 1;                   // channel half: floats [4k, 4k+4)
    if (pA >= half) return;
    int pB = pA + half;               // second point (may be >= n at the tail)
    bool hasB = (pB < n);

    const int RS = W * C;             // row stride in floats

    // Coord loads (streaming; broadcast within lane pair).
    float2 xyA = __ldcs(reinterpret_cast<const float2*>(coords) + pA);
    float2 xyB = hasB ? __ldcs(reinterpret_cast<const float2*>(coords) + pB)
                      : make_float2(1.0f, 1.0f);

    PointCtx cA = make_ctx(xyA, k);
    PointCtx cB = make_ctx(xyB, k);

    const float4* A00 = reinterpret_cast<const float4*>(visible + cA.base);
    const float4* A01 = reinterpret_cast<const float4*>(visible + cA.base + C);
    const float4* A10 = reinterpret_cast<const float4*>(visible + cA.base + RS);
    const float4* A11 = reinterpret_cast<const float4*>(visible + cA.base + RS + C);
    const float4* B00 = reinterpret_cast<const float4*>(visible + cB.base);
    const float4* B01 = reinterpret_cast<const float4*>(visible + cB.base + C);
    const float4* B10 = reinterpret_cast<const float4*>(visible + cB.base + RS);
    const float4* B11 = reinterpret_cast<const float4*>(visible + cB.base + RS + C);

    // Front-batch all 8 gathers for deep MLP.
    float4 a00 = __ldg(A00);
    float4 a01 = __ldg(A01);
    float4 a10 = __ldg(A10);
    float4 a11 = __ldg(A11);
    float4 b00 = __ldg(B00);
    float4 b01 = __ldg(B01);
    float4 b10 = __ldg(B10);
    float4 b11 = __ldg(B11);

    float4 oA = blend(cA, a00, a01, a10, a11);
    float4 oB = blend(cB, b00, b01, b10, b11);

    // Consecutive lanes write consecutive float4s — fully coalesced; streaming stores.
    __stcs(reinterpret_cast<float4*>(out + pA * C + 4 * k), oA);
    if (hasB)
        __stcs(reinterpret_cast<float4*>(out + pB * C + 4 * k), oB);
}

extern "C" void kernel_launch(void* const* d_in, const int* in_sizes, int n_in,
                              void* d_out, int out_size)
{
    const float* coords  = (const float*)d_in[0];  // [N, 2] fp32
    const float* visible = (const float*)d_in[1];  // [H, W, C] fp32
    float* out = (float*)d_out;                    // [N, C] fp32

    int n = in_sizes[0] / 2;   // number of points
    (void)n_in; (void)out_size;

    int half = (n + 1) >> 1;
    int total = 2 * half;      // 2 threads per point-slot, 2 points per thread
    int threads = 256;
    int blocks = (total + threads - 1) / threads;
    idx2pixel_kernel<<<blocks, threads>>>(coords, visible, out, n);
}